// round 1
// baseline (speedup 1.0000x reference)
#include <cuda_runtime.h>
#include <math.h>

// Problem constants
#define NB 2
#define LQ 1024
#define DM 4544          // = 71 * 64
#define HQ 71
#define DK 64
#define FUSED_COLS 4672  // DM + 2*DK  (71 q heads + k + v, each 64)

// Scratch (allocation-free: __device__ globals)
__device__ float g_fused[NB * LQ * FUSED_COLS];  // qkv output, rope applied in-place
__device__ float g_attn [NB * LQ * DM];          // attention output (n, l, H*DK)

// ---------------------------------------------------------------------------
// SGEMM (NT): C[M,N] = A[M,K] * B[N,K]^T, all row-major.
// BM=128, BN=64, BK=16, 256 threads, 8x4 micro-tile per thread.
// Requires: M%128==0, N%64==0, K%16==0, K%4==0 for float4.
// ---------------------------------------------------------------------------
__global__ __launch_bounds__(256) void sgemm_nt(
    const float* __restrict__ A, const float* __restrict__ B,
    float* __restrict__ C, int M, int N, int K)
{
    __shared__ float As[16][128];   // [k][m] transposed
    __shared__ float Bs[16][64];    // [k][n] transposed

    const int tid = threadIdx.x;
    const int ty = tid >> 4;        // 0..15  -> 8 rows each
    const int tx = tid & 15;        // 0..15  -> 4 cols each
    const int bm = blockIdx.y * 128;
    const int bn = blockIdx.x * 64;

    float acc[8][4];
#pragma unroll
    for (int i = 0; i < 8; i++)
#pragma unroll
        for (int j = 0; j < 4; j++) acc[i][j] = 0.0f;

    const int ar  = tid >> 2;   // 0..63 (plus 64 on second load)
    const int akg = tid & 3;    // which float4 along k

    for (int k0 = 0; k0 < K; k0 += 16) {
        // Load A tile (128 x 16): 2 float4 per thread, store transposed
#pragma unroll
        for (int lp = 0; lp < 2; lp++) {
            int r = ar + lp * 64;
            float4 v = *(const float4*)(A + (size_t)(bm + r) * K + k0 + akg * 4);
            As[akg * 4 + 0][r] = v.x;
            As[akg * 4 + 1][r] = v.y;
            As[akg * 4 + 2][r] = v.z;
            As[akg * 4 + 3][r] = v.w;
        }
        // Load B tile (64 x 16): 1 float4 per thread, store transposed
        {
            int r  = tid >> 2;
            int kg = tid & 3;
            float4 v = *(const float4*)(B + (size_t)(bn + r) * K + k0 + kg * 4);
            Bs[kg * 4 + 0][r] = v.x;
            Bs[kg * 4 + 1][r] = v.y;
            Bs[kg * 4 + 2][r] = v.z;
            Bs[kg * 4 + 3][r] = v.w;
        }
        __syncthreads();

#pragma unroll
        for (int kk = 0; kk < 16; kk++) {
            float a[8], b[4];
            *(float4*)&a[0] = *(const float4*)&As[kk][ty * 8];
            *(float4*)&a[4] = *(const float4*)&As[kk][ty * 8 + 4];
            *(float4*)&b[0] = *(const float4*)&Bs[kk][tx * 4];
#pragma unroll
            for (int i = 0; i < 8; i++)
#pragma unroll
                for (int j = 0; j < 4; j++)
                    acc[i][j] = fmaf(a[i], b[j], acc[i][j]);
        }
        __syncthreads();
    }

#pragma unroll
    for (int i = 0; i < 8; i++) {
        float4 v = make_float4(acc[i][0], acc[i][1], acc[i][2], acc[i][3]);
        *(float4*)(C + (size_t)(bm + ty * 8 + i) * N + bn + tx * 4) = v;
    }
}

// ---------------------------------------------------------------------------
// RoPE applied in-place to q (71 heads) and k inside g_fused.
// One block per token; each thread handles (head, j) rotation pairs.
// out[j]    = x[j]*cos(t*f_j)    - x[j+32]*sin(t*f_j)
// out[j+32] = x[j+32]*cos(t*f_j) + x[j]*sin(t*f_j)
// ---------------------------------------------------------------------------
__global__ __launch_bounds__(256) void rope_kernel()
{
    const int token = blockIdx.x;           // 0 .. NB*LQ-1
    const int t = token & (LQ - 1);
    float* base = g_fused + (size_t)token * FUSED_COLS;

    for (int p = threadIdx.x; p < (HQ + 1) * 32; p += blockDim.x) {
        int head = p >> 5;
        int j = p & 31;
        float* hb = base + (head < HQ ? head * DK : DM);  // 71 q heads, then k
        float inv = powf(10000.0f, -(float)j * (1.0f / 32.0f));
        float ang = (float)t * inv;
        float s, c;
        sincosf(ang, &s, &c);
        float x1 = hb[j];
        float x2 = hb[j + 32];
        hb[j]      = x1 * c - x2 * s;
        hb[j + 32] = x2 * c + x1 * s;
    }
}

// ---------------------------------------------------------------------------
// Flash attention, fp32, causal, MQA (shared K/V per batch).
// Grid: (L/64, HQ, NB). Block: 256 threads as 16x16 (ty rows, tx cols).
// Each thread: 4x4 of S / P and 4x4 of O.
// smem: Qs[64][65] (d-major), Ks[64][65] (d-major), Ps[64][65] (j-major),
//       Vs[64][64] (j-major).
// ---------------------------------------------------------------------------
#define ATT_SMEM_FLOATS (3 * 64 * 65 + 64 * 64)
#define ATT_SMEM_BYTES  (ATT_SMEM_FLOATS * 4)

__global__ __launch_bounds__(256) void attn_kernel()
{
    extern __shared__ float sm[];
    float* Qs = sm;                 // [d][i], stride 65
    float* Ks = Qs + 64 * 65;       // [d][j], stride 65
    float* Ps = Ks + 64 * 65;       // [j][i], stride 65
    float* Vs = Ps + 64 * 65;       // [j][d], stride 64

    const int qb = blockIdx.x;
    const int h  = blockIdx.y;
    const int n  = blockIdx.z;
    const int tid = threadIdx.x;
    const int ty = tid >> 4;        // query-row group (4 rows)
    const int tx = tid & 15;        // key-col / dim group (4 cols)

    const float* fused = g_fused + (size_t)n * LQ * FUSED_COLS;

    // Load Q tile transposed: Qs[d][i]
#pragma unroll
    for (int r = 0; r < 4; r++) {
        int lin = tid + r * 256;
        int i  = lin >> 4;
        int dg = lin & 15;
        float4 v = *(const float4*)(fused + (size_t)(qb * 64 + i) * FUSED_COLS + h * DK + dg * 4);
        Qs[(dg * 4 + 0) * 65 + i] = v.x;
        Qs[(dg * 4 + 1) * 65 + i] = v.y;
        Qs[(dg * 4 + 2) * 65 + i] = v.z;
        Qs[(dg * 4 + 3) * 65 + i] = v.w;
    }

    float m[4], l[4], O[4][4];
#pragma unroll
    for (int i = 0; i < 4; i++) {
        m[i] = -INFINITY;
        l[i] = 0.0f;
#pragma unroll
        for (int j = 0; j < 4; j++) O[i][j] = 0.0f;
    }

    const float scale = 0.125f;   // 1/sqrt(64)

    for (int jb = 0; jb <= qb; jb++) {
        __syncthreads();  // also covers the Q-load on first iteration

        // Load K (transposed, stride 65) and V (natural, stride 64)
#pragma unroll
        for (int r = 0; r < 4; r++) {
            int lin = tid + r * 256;
            int j  = lin >> 4;
            int dg = lin & 15;
            const float* row = fused + (size_t)(jb * 64 + j) * FUSED_COLS;
            float4 kv = *(const float4*)(row + DM + dg * 4);
            Ks[(dg * 4 + 0) * 65 + j] = kv.x;
            Ks[(dg * 4 + 1) * 65 + j] = kv.y;
            Ks[(dg * 4 + 2) * 65 + j] = kv.z;
            Ks[(dg * 4 + 3) * 65 + j] = kv.w;
            float4 vv = *(const float4*)(row + DM + DK + dg * 4);
            *(float4*)(Vs + j * 64 + dg * 4) = vv;
        }
        __syncthreads();

        // S = Q * K^T (4x4 per thread)
        float S[4][4];
#pragma unroll
        for (int i = 0; i < 4; i++)
#pragma unroll
            for (int j = 0; j < 4; j++) S[i][j] = 0.0f;

#pragma unroll 8
        for (int d = 0; d < 64; d++) {
            float q0 = Qs[d * 65 + ty * 4 + 0];
            float q1 = Qs[d * 65 + ty * 4 + 1];
            float q2 = Qs[d * 65 + ty * 4 + 2];
            float q3 = Qs[d * 65 + ty * 4 + 3];
            float k0 = Ks[d * 65 + tx * 4 + 0];
            float k1 = Ks[d * 65 + tx * 4 + 1];
            float k2 = Ks[d * 65 + tx * 4 + 2];
            float k3 = Ks[d * 65 + tx * 4 + 3];
            S[0][0] = fmaf(q0, k0, S[0][0]); S[0][1] = fmaf(q0, k1, S[0][1]);
            S[0][2] = fmaf(q0, k2, S[0][2]); S[0][3] = fmaf(q0, k3, S[0][3]);
            S[1][0] = fmaf(q1, k0, S[1][0]); S[1][1] = fmaf(q1, k1, S[1][1]);
            S[1][2] = fmaf(q1, k2, S[1][2]); S[1][3] = fmaf(q1, k3, S[1][3]);
            S[2][0] = fmaf(q2, k0, S[2][0]); S[2][1] = fmaf(q2, k1, S[2][1]);
            S[2][2] = fmaf(q2, k2, S[2][2]); S[2][3] = fmaf(q2, k3, S[2][3]);
            S[3][0] = fmaf(q3, k0, S[3][0]); S[3][1] = fmaf(q3, k1, S[3][1]);
            S[3][2] = fmaf(q3, k2, S[3][2]); S[3][3] = fmaf(q3, k3, S[3][3]);
        }

        // Scale + causal mask (only diagonal block needs masking)
        if (jb == qb) {
#pragma unroll
            for (int i = 0; i < 4; i++)
#pragma unroll
                for (int j = 0; j < 4; j++)
                    S[i][j] = (tx * 4 + j <= ty * 4 + i) ? S[i][j] * scale : -1e30f;
        } else {
#pragma unroll
            for (int i = 0; i < 4; i++)
#pragma unroll
                for (int j = 0; j < 4; j++)
                    S[i][j] *= scale;
        }

        // Online softmax per row (rows 4*ty..4*ty+3; reduce across 16 tx lanes)
#pragma unroll
        for (int i = 0; i < 4; i++) {
            float mx = fmaxf(fmaxf(S[i][0], S[i][1]), fmaxf(S[i][2], S[i][3]));
#pragma unroll
            for (int off = 8; off >= 1; off >>= 1)
                mx = fmaxf(mx, __shfl_xor_sync(0xffffffffu, mx, off));
            float mnew  = fmaxf(m[i], mx);
            float alpha = __expf(m[i] - mnew);
            float rs = 0.0f;
#pragma unroll
            for (int j = 0; j < 4; j++) {
                float p = __expf(S[i][j] - mnew);
                S[i][j] = p;
                rs += p;
            }
#pragma unroll
            for (int off = 8; off >= 1; off >>= 1)
                rs += __shfl_xor_sync(0xffffffffu, rs, off);
            l[i] = l[i] * alpha + rs;
            m[i] = mnew;
#pragma unroll
            for (int d = 0; d < 4; d++) O[i][d] *= alpha;
        }

        // Stage P to smem: Ps[j][i], stride 65
#pragma unroll
        for (int i = 0; i < 4; i++)
#pragma unroll
            for (int j = 0; j < 4; j++)
                Ps[(tx * 4 + j) * 65 + ty * 4 + i] = S[i][j];
        __syncthreads();

        // O += P * V  (inner dim j = 64 keys)
#pragma unroll 8
        for (int j = 0; j < 64; j++) {
            float p0 = Ps[j * 65 + ty * 4 + 0];
            float p1 = Ps[j * 65 + ty * 4 + 1];
            float p2 = Ps[j * 65 + ty * 4 + 2];
            float p3 = Ps[j * 65 + ty * 4 + 3];
            float4 v = *(const float4*)(Vs + j * 64 + tx * 4);
            O[0][0] = fmaf(p0, v.x, O[0][0]); O[0][1] = fmaf(p0, v.y, O[0][1]);
            O[0][2] = fmaf(p0, v.z, O[0][2]); O[0][3] = fmaf(p0, v.w, O[0][3]);
            O[1][0] = fmaf(p1, v.x, O[1][0]); O[1][1] = fmaf(p1, v.y, O[1][1]);
            O[1][2] = fmaf(p1, v.z, O[1][2]); O[1][3] = fmaf(p1, v.w, O[1][3]);
            O[2][0] = fmaf(p2, v.x, O[2][0]); O[2][1] = fmaf(p2, v.y, O[2][1]);
            O[2][2] = fmaf(p2, v.z, O[2][2]); O[2][3] = fmaf(p2, v.w, O[2][3]);
            O[3][0] = fmaf(p3, v.x, O[3][0]); O[3][1] = fmaf(p3, v.y, O[3][1]);
            O[3][2] = fmaf(p3, v.z, O[3][2]); O[3][3] = fmaf(p3, v.w, O[3][3]);
        }
    }

    // Finalize: divide by l, write to g_attn (n, l, H*DK)
    float* outp = g_attn + ((size_t)n * LQ + qb * 64) * DM + h * DK;
#pragma unroll
    for (int i = 0; i < 4; i++) {
        float inv = 1.0f / l[i];
        float4 o = make_float4(O[i][0] * inv, O[i][1] * inv,
                               O[i][2] * inv, O[i][3] * inv);
        *(float4*)(outp + (size_t)(ty * 4 + i) * DM + tx * 4) = o;
    }
}

// ---------------------------------------------------------------------------
// Launch
// ---------------------------------------------------------------------------
extern "C" void kernel_launch(void* const* d_in, const int* in_sizes, int n_in,
                              void* d_out, int out_size)
{
    const float* hidden  = (const float*)d_in[0];  // (2, 1024, 4544)
    const float* w_qkv   = (const float*)d_in[1];  // (4672, 4544)
    const float* w_dense = (const float*)d_in[2];  // (4544, 4544)
    float* out = (float*)d_out;                    // (2, 1024, 4544)

    float *fused_ptr, *attn_ptr;
    cudaGetSymbolAddress((void**)&fused_ptr, g_fused);
    cudaGetSymbolAddress((void**)&attn_ptr, g_attn);

    cudaFuncSetAttribute(attn_kernel,
                         cudaFuncAttributeMaxDynamicSharedMemorySize,
                         ATT_SMEM_BYTES);

    // 1) QKV GEMM: (2048 x 4544) * (4672 x 4544)^T -> g_fused
    {
        dim3 grid(FUSED_COLS / 64, (NB * LQ) / 128);
        sgemm_nt<<<grid, 256>>>(hidden, w_qkv, fused_ptr, NB * LQ, FUSED_COLS, DM);
    }
    // 2) RoPE in-place on q and k
    rope_kernel<<<NB * LQ, 256>>>();
    // 3) Causal MQA flash attention -> g_attn
    {
        dim3 grid(LQ / 64, HQ, NB);
        attn_kernel<<<grid, 256, ATT_SMEM_BYTES>>>();
    }
    // 4) Dense GEMM: (2048 x 4544) * (4544 x 4544)^T -> out
    {
        dim3 grid(DM / 64, (NB * LQ) / 128);
        sgemm_nt<<<grid, 256>>>(attn_ptr, w_dense, out, NB * LQ, DM, DM);
    }
}

// round 6
// speedup vs baseline: 2.1533x; 2.1533x over previous
#include <cuda_runtime.h>
#include <cuda_bf16.h>
#include <math.h>
#include <stdint.h>

// Problem constants
#define NB 2
#define LQ 1024
#define DM 4544          // = 71 * 64
#define HQ 71
#define DK 64
#define KDIM 4544
#define NQKV 4672        // DM + 2*DK
#define NQKV_PAD 4736    // 37 * 128
#define ND_PAD 4608      // 36 * 128
#define FSTRIDE NQKV_PAD

// ---------------------------------------------------------------------------
// Scratch (__device__ globals; allocation-free)
// ---------------------------------------------------------------------------
__device__ float g_fused[NB * LQ * FSTRIDE];     // qkv output (padded stride)
__device__ float g_attn [NB * LQ * DM];          // attention output
__device__ __nv_bfloat16 g_xh[NB * LQ * KDIM];   // hidden hi/lo
__device__ __nv_bfloat16 g_xl[NB * LQ * KDIM];
__device__ __nv_bfloat16 g_oh[NB * LQ * KDIM];   // attn-out hi/lo
__device__ __nv_bfloat16 g_ol[NB * LQ * KDIM];
__device__ __nv_bfloat16 g_wqh[NQKV_PAD * KDIM]; // w_qkv hi/lo (row-padded)
__device__ __nv_bfloat16 g_wql[NQKV_PAD * KDIM];
__device__ __nv_bfloat16 g_wdh[ND_PAD * KDIM];   // w_dense hi/lo (row-padded)
__device__ __nv_bfloat16 g_wdl[ND_PAD * KDIM];

// ---------------------------------------------------------------------------
// PTX helpers (compute_103-safe: cp.async + ldmatrix + mma.sync only)
// ---------------------------------------------------------------------------
__device__ __forceinline__ uint32_t smem_u32(const void* p) {
    uint32_t a;
    asm("{ .reg .u64 t; cvta.to.shared.u64 t, %1; cvt.u32.u64 %0, t; }"
        : "=r"(a) : "l"(p));
    return a;
}

#define CP_ASYNC16(dst, src) \
    asm volatile("cp.async.cg.shared.global [%0], [%1], 16;" \
                 :: "r"(dst), "l"(src) : "memory")
#define CP_COMMIT() asm volatile("cp.async.commit_group;" ::: "memory")
template <int N>
__device__ __forceinline__ void cp_wait_group() {
    asm volatile("cp.async.wait_group %0;" :: "n"(N) : "memory");
}

#define LDSM_X4(r, addr) \
    asm volatile("ldmatrix.sync.aligned.m8n8.x4.shared.b16 {%0,%1,%2,%3}, [%4];" \
                 : "=r"((r)[0]), "=r"((r)[1]), "=r"((r)[2]), "=r"((r)[3]) \
                 : "r"(addr))

#define MMA_BF16(c, a, b) \
    asm volatile("mma.sync.aligned.m16n8k16.row.col.f32.bf16.bf16.f32 " \
                 "{%0,%1,%2,%3}, {%4,%5,%6,%7}, {%8,%9}, {%0,%1,%2,%3};" \
                 : "+f"((c)[0]), "+f"((c)[1]), "+f"((c)[2]), "+f"((c)[3]) \
                 : "r"((a)[0]), "r"((a)[1]), "r"((a)[2]), "r"((a)[3]), \
                   "r"((b)[0]), "r"((b)[1]))

// ---------------------------------------------------------------------------
// fp32 -> bf16 hi/lo split (with zero-padding past n_real)
// ---------------------------------------------------------------------------
__global__ __launch_bounds__(256) void convert_split(
    const float* __restrict__ src, __nv_bfloat16* __restrict__ hh,
    __nv_bfloat16* __restrict__ ll, long n_real, long n_pad)
{
    long idx = ((long)blockIdx.x * 256 + threadIdx.x) * 4;
    if (idx >= n_pad) return;
    float4 v = make_float4(0.f, 0.f, 0.f, 0.f);
    if (idx < n_real) v = *(const float4*)(src + idx);

    __nv_bfloat16 h0 = __float2bfloat16(v.x);
    __nv_bfloat16 h1 = __float2bfloat16(v.y);
    __nv_bfloat16 h2 = __float2bfloat16(v.z);
    __nv_bfloat16 h3 = __float2bfloat16(v.w);
    __nv_bfloat16 l0 = __float2bfloat16(v.x - __bfloat162float(h0));
    __nv_bfloat16 l1 = __float2bfloat16(v.y - __bfloat162float(h1));
    __nv_bfloat16 l2 = __float2bfloat16(v.z - __bfloat162float(h2));
    __nv_bfloat16 l3 = __float2bfloat16(v.w - __bfloat162float(h3));

    __nv_bfloat162 hp0 = __nv_bfloat162(h0, h1), hp1 = __nv_bfloat162(h2, h3);
    __nv_bfloat162 lp0 = __nv_bfloat162(l0, l1), lp1 = __nv_bfloat162(l2, l3);
    *(uint2*)(hh + idx) = make_uint2(*(uint32_t*)&hp0, *(uint32_t*)&hp1);
    *(uint2*)(ll + idx) = make_uint2(*(uint32_t*)&lp0, *(uint32_t*)&lp1);
}

// ---------------------------------------------------------------------------
// HMMA GEMM, bf16x3 split: C[M,N] = A[M,K] * B[N,K]^T  (fp32-accurate)
// BM=128, BN=128, BK=32; 8 warps (2m x 4n), warp tile 64x32, m16n8k16.
// 2-stage cp.async double buffer. Tiles in smem: [Ah][Al][Bh][Bl],
// each 128 rows x (32+8) bf16 (SKEW=8 -> conflict-free ldmatrix).
// ---------------------------------------------------------------------------
#define BKI 32
#define SKEW 8
#define LDT (BKI + SKEW)             // 40 elements
#define ROWB (LDT * 2)               // 80 bytes per row
#define TILEB (128 * ROWB)           // 10240 bytes
#define STAGEB (4 * TILEB)           // 40960 bytes
#define GEMM_SMEM (2 * STAGEB)       // 81920 bytes
#define NKIT (KDIM / BKI)            // 142

__device__ __forceinline__ void load_stage(
    uint32_t sb, int stage, int k0, int tid, const char* const* srcs)
{
    size_t koff = (size_t)k0 * 2;
#pragma unroll
    for (int t = 0; t < 8; t++) {
        int c    = tid + t * 256;        // 0..2047
        int tile = c >> 9;               // 512 chunks per tile
        int row  = (c >> 2) & 127;
        int q    = c & 3;
        const char* src = srcs[tile] + (size_t)row * (KDIM * 2) + koff + q * 16;
        uint32_t dst = sb + (uint32_t)stage * STAGEB + (uint32_t)tile * TILEB
                     + (uint32_t)(row * ROWB + q * 16);
        CP_ASYNC16(dst, src);
    }
    CP_COMMIT();
}

__global__ __launch_bounds__(256, 1) void gemm_bf16x3(
    const __nv_bfloat16* __restrict__ Ah, const __nv_bfloat16* __restrict__ Al,
    const __nv_bfloat16* __restrict__ Bh, const __nv_bfloat16* __restrict__ Bl,
    float* __restrict__ C, int ldc, int n_real)
{
    extern __shared__ char smem[];
    uint32_t sb = smem_u32(smem);
    const int tid  = threadIdx.x;
    const int warp = tid >> 5;
    const int lane = tid & 31;
    const int bm = blockIdx.y * 128;
    const int bn = blockIdx.x * 128;

    const int wm = (warp >> 2) * 64;     // warp m offset (0 or 64)
    const int wn = (warp & 3) * 32;      // warp n offset (0,32,64,96)

    const char* srcs[4] = {
        (const char*)Ah + (size_t)bm * KDIM * 2,
        (const char*)Al + (size_t)bm * KDIM * 2,
        (const char*)Bh + (size_t)bn * KDIM * 2,
        (const char*)Bl + (size_t)bn * KDIM * 2
    };

    // ldmatrix lane addressing
    const int lr = lane & 7;
    const int ma = lane >> 3;
    // A mats: (m0-7,k0-7),(m8-15,k0-7),(m0-7,k8-15),(m8-15,k8-15)
    const uint32_t aoff = (uint32_t)((((ma & 1) * 8 + lr) * LDT + (ma >> 1) * 8) * 2);
    // B mats: (n0-7,k0-7),(n0-7,k8-15),(n8-15,k0-7),(n8-15,k8-15)
    const uint32_t boff = (uint32_t)((((ma >> 1) * 8 + lr) * LDT + (ma & 1) * 8) * 2);

    const uint32_t aBase = sb + (uint32_t)(wm * ROWB) + aoff;              // Ah tile
    const uint32_t bBase = sb + 2u * TILEB + (uint32_t)(wn * ROWB) + boff; // Bh tile

    float acc[4][4][4];
#pragma unroll
    for (int i = 0; i < 4; i++)
#pragma unroll
        for (int j = 0; j < 4; j++)
#pragma unroll
            for (int k = 0; k < 4; k++) acc[i][j][k] = 0.0f;

    load_stage(sb, 0, 0, tid, srcs);

    for (int it = 0; it < NKIT; it++) {
        const int s = it & 1;
        if (it + 1 < NKIT) {
            load_stage(sb, s ^ 1, (it + 1) * BKI, tid, srcs);
            cp_wait_group<1>();
        } else {
            cp_wait_group<0>();
        }
        __syncthreads();

        const uint32_t so = (uint32_t)s * STAGEB;
#pragma unroll
        for (int ks = 0; ks < 2; ks++) {
            const uint32_t kb = (uint32_t)(ks * 32);   // 16 cols * 2B
            uint32_t ah[4][4], al[4][4], bh[4][2], bl[4][2];
#pragma unroll
            for (int mt = 0; mt < 4; mt++) {
                uint32_t a = aBase + so + (uint32_t)(mt * 16 * ROWB) + kb;
                LDSM_X4(ah[mt], a);
                LDSM_X4(al[mt], a + TILEB);
            }
#pragma unroll
            for (int nt2 = 0; nt2 < 2; nt2++) {
                uint32_t b = bBase + so + (uint32_t)(nt2 * 16 * ROWB) + kb;
                LDSM_X4(&bh[nt2 * 2][0], b);
                LDSM_X4(&bl[nt2 * 2][0], b + TILEB);
            }
#pragma unroll
            for (int mt = 0; mt < 4; mt++) {
#pragma unroll
                for (int nt = 0; nt < 4; nt++) {
                    MMA_BF16(acc[mt][nt], ah[mt], bh[nt]);
                    MMA_BF16(acc[mt][nt], ah[mt], bl[nt]);
                    MMA_BF16(acc[mt][nt], al[mt], bh[nt]);
                }
            }
        }
        __syncthreads();
    }

    // Epilogue: c0,c1 at (row, col..col+1), c2,c3 at (row+8, col..col+1)
    const int r0 = bm + wm + (lane >> 2);
    const int c0 = bn + wn + (lane & 3) * 2;
#pragma unroll
    for (int mt = 0; mt < 4; mt++) {
#pragma unroll
        for (int nt = 0; nt < 4; nt++) {
            int col = c0 + nt * 8;
            if (col < n_real) {
                int row = r0 + mt * 16;
                *(float2*)(C + (size_t)row * ldc + col) =
                    make_float2(acc[mt][nt][0], acc[mt][nt][1]);
                *(float2*)(C + (size_t)(row + 8) * ldc + col) =
                    make_float2(acc[mt][nt][2], acc[mt][nt][3]);
            }
        }
    }
}

// ---------------------------------------------------------------------------
// RoPE in-place on q (71 heads) and k inside g_fused (stride FSTRIDE).
// ---------------------------------------------------------------------------
__global__ __launch_bounds__(256) void rope_kernel()
{
    const int token = blockIdx.x;
    const int t = token & (LQ - 1);
    float* base = g_fused + (size_t)token * FSTRIDE;

    for (int p = threadIdx.x; p < (HQ + 1) * 32; p += blockDim.x) {
        int head = p >> 5;
        int j = p & 31;
        float* hb = base + (head < HQ ? head * DK : DM);
        float inv = powf(10000.0f, -(float)j * (1.0f / 32.0f));
        float ang = (float)t * inv;
        float s, c;
        sincosf(ang, &s, &c);
        float x1 = hb[j];
        float x2 = hb[j + 32];
        hb[j]      = x1 * c - x2 * s;
        hb[j + 32] = x2 * c + x1 * s;
    }
}

// ---------------------------------------------------------------------------
// Flash attention, fp32, causal, MQA (shared K/V per batch).
// ---------------------------------------------------------------------------
#define ATT_SMEM_FLOATS (3 * 64 * 65 + 64 * 64)
#define ATT_SMEM_BYTES  (ATT_SMEM_FLOATS * 4)

__global__ __launch_bounds__(256) void attn_kernel()
{
    extern __shared__ float sm[];
    float* Qs = sm;
    float* Ks = Qs + 64 * 65;
    float* Ps = Ks + 64 * 65;
    float* Vs = Ps + 64 * 65;

    const int qb = blockIdx.x;
    const int h  = blockIdx.y;
    const int n  = blockIdx.z;
    const int tid = threadIdx.x;
    const int ty = tid >> 4;
    const int tx = tid & 15;

    const float* fused = g_fused + (size_t)n * LQ * FSTRIDE;

#pragma unroll
    for (int r = 0; r < 4; r++) {
        int lin = tid + r * 256;
        int i  = lin >> 4;
        int dg = lin & 15;
        float4 v = *(const float4*)(fused + (size_t)(qb * 64 + i) * FSTRIDE + h * DK + dg * 4);
        Qs[(dg * 4 + 0) * 65 + i] = v.x;
        Qs[(dg * 4 + 1) * 65 + i] = v.y;
        Qs[(dg * 4 + 2) * 65 + i] = v.z;
        Qs[(dg * 4 + 3) * 65 + i] = v.w;
    }

    float m[4], l[4], O[4][4];
#pragma unroll
    for (int i = 0; i < 4; i++) {
        m[i] = -INFINITY;
        l[i] = 0.0f;
#pragma unroll
        for (int j = 0; j < 4; j++) O[i][j] = 0.0f;
    }

    const float scale = 0.125f;

    for (int jb = 0; jb <= qb; jb++) {
        __syncthreads();

#pragma unroll
        for (int r = 0; r < 4; r++) {
            int lin = tid + r * 256;
            int j  = lin >> 4;
            int dg = lin & 15;
            const float* row = fused + (size_t)(jb * 64 + j) * FSTRIDE;
            float4 kv = *(const float4*)(row + DM + dg * 4);
            Ks[(dg * 4 + 0) * 65 + j] = kv.x;
            Ks[(dg * 4 + 1) * 65 + j] = kv.y;
            Ks[(dg * 4 + 2) * 65 + j] = kv.z;
            Ks[(dg * 4 + 3) * 65 + j] = kv.w;
            float4 vv = *(const float4*)(row + DM + DK + dg * 4);
            *(float4*)(Vs + j * 64 + dg * 4) = vv;
        }
        __syncthreads();

        float S[4][4];
#pragma unroll
        for (int i = 0; i < 4; i++)
#pragma unroll
            for (int j = 0; j < 4; j++) S[i][j] = 0.0f;

#pragma unroll 8
        for (int d = 0; d < 64; d++) {
            float q0 = Qs[d * 65 + ty * 4 + 0];
            float q1 = Qs[d * 65 + ty * 4 + 1];
            float q2 = Qs[d * 65 + ty * 4 + 2];
            float q3 = Qs[d * 65 + ty * 4 + 3];
            float k0 = Ks[d * 65 + tx * 4 + 0];
            float k1 = Ks[d * 65 + tx * 4 + 1];
            float k2 = Ks[d * 65 + tx * 4 + 2];
            float k3 = Ks[d * 65 + tx * 4 + 3];
            S[0][0] = fmaf(q0, k0, S[0][0]); S[0][1] = fmaf(q0, k1, S[0][1]);
            S[0][2] = fmaf(q0, k2, S[0][2]); S[0][3] = fmaf(q0, k3, S[0][3]);
            S[1][0] = fmaf(q1, k0, S[1][0]); S[1][1] = fmaf(q1, k1, S[1][1]);
            S[1][2] = fmaf(q1, k2, S[1][2]); S[1][3] = fmaf(q1, k3, S[1][3]);
            S[2][0] = fmaf(q2, k0, S[2][0]); S[2][1] = fmaf(q2, k1, S[2][1]);
            S[2][2] = fmaf(q2, k2, S[2][2]); S[2][3] = fmaf(q2, k3, S[2][3]);
            S[3][0] = fmaf(q3, k0, S[3][0]); S[3][1] = fmaf(q3, k1, S[3][1]);
            S[3][2] = fmaf(q3, k2, S[3][2]); S[3][3] = fmaf(q3, k3, S[3][3]);
        }

        if (jb == qb) {
#pragma unroll
            for (int i = 0; i < 4; i++)
#pragma unroll
                for (int j = 0; j < 4; j++)
                    S[i][j] = (tx * 4 + j <= ty * 4 + i) ? S[i][j] * scale : -1e30f;
        } else {
#pragma unroll
            for (int i = 0; i < 4; i++)
#pragma unroll
                for (int j = 0; j < 4; j++)
                    S[i][j] *= scale;
        }

#pragma unroll
        for (int i = 0; i < 4; i++) {
            float mx = fmaxf(fmaxf(S[i][0], S[i][1]), fmaxf(S[i][2], S[i][3]));
#pragma unroll
            for (int off = 8; off >= 1; off >>= 1)
                mx = fmaxf(mx, __shfl_xor_sync(0xffffffffu, mx, off));
            float mnew  = fmaxf(m[i], mx);
            float alpha = __expf(m[i] - mnew);
            float rs = 0.0f;
#pragma unroll
            for (int j = 0; j < 4; j++) {
                float p = __expf(S[i][j] - mnew);
                S[i][j] = p;
                rs += p;
            }
#pragma unroll
            for (int off = 8; off >= 1; off >>= 1)
                rs += __shfl_xor_sync(0xffffffffu, rs, off);
            l[i] = l[i] * alpha + rs;
            m[i] = mnew;
#pragma unroll
            for (int d = 0; d < 4; d++) O[i][d] *= alpha;
        }

#pragma unroll
        for (int i = 0; i < 4; i++)
#pragma unroll
            for (int j = 0; j < 4; j++)
                Ps[(tx * 4 + j) * 65 + ty * 4 + i] = S[i][j];
        __syncthreads();

#pragma unroll 8
        for (int j = 0; j < 64; j++) {
            float p0 = Ps[j * 65 + ty * 4 + 0];
            float p1 = Ps[j * 65 + ty * 4 + 1];
            float p2 = Ps[j * 65 + ty * 4 + 2];
            float p3 = Ps[j * 65 + ty * 4 + 3];
            float4 v = *(const float4*)(Vs + j * 64 + tx * 4);
            O[0][0] = fmaf(p0, v.x, O[0][0]); O[0][1] = fmaf(p0, v.y, O[0][1]);
            O[0][2] = fmaf(p0, v.z, O[0][2]); O[0][3] = fmaf(p0, v.w, O[0][3]);
            O[1][0] = fmaf(p1, v.x, O[1][0]); O[1][1] = fmaf(p1, v.y, O[1][1]);
            O[1][2] = fmaf(p1, v.z, O[1][2]); O[1][3] = fmaf(p1, v.w, O[1][3]);
            O[2][0] = fmaf(p2, v.x, O[2][0]); O[2][1] = fmaf(p2, v.y, O[2][1]);
            O[2][2] = fmaf(p2, v.z, O[2][2]); O[2][3] = fmaf(p2, v.w, O[2][3]);
            O[3][0] = fmaf(p3, v.x, O[3][0]); O[3][1] = fmaf(p3, v.y, O[3][1]);
            O[3][2] = fmaf(p3, v.z, O[3][2]); O[3][3] = fmaf(p3, v.w, O[3][3]);
        }
    }

    float* outp = g_attn + ((size_t)n * LQ + qb * 64) * DM + h * DK;
#pragma unroll
    for (int i = 0; i < 4; i++) {
        float inv = 1.0f / l[i];
        float4 o = make_float4(O[i][0] * inv, O[i][1] * inv,
                               O[i][2] * inv, O[i][3] * inv);
        *(float4*)(outp + (size_t)(ty * 4 + i) * DM + tx * 4) = o;
    }
}

// ---------------------------------------------------------------------------
// Launch
// ---------------------------------------------------------------------------
extern "C" void kernel_launch(void* const* d_in, const int* in_sizes, int n_in,
                              void* d_out, int out_size)
{
    const float* hidden  = (const float*)d_in[0];
    const float* w_qkv   = (const float*)d_in[1];
    const float* w_dense = (const float*)d_in[2];
    float* out = (float*)d_out;

    float *fused_ptr, *attn_ptr;
    __nv_bfloat16 *xh, *xl, *oh, *ol, *wqh, *wql, *wdh, *wdl;
    cudaGetSymbolAddress((void**)&fused_ptr, g_fused);
    cudaGetSymbolAddress((void**)&attn_ptr, g_attn);
    cudaGetSymbolAddress((void**)&xh, g_xh);
    cudaGetSymbolAddress((void**)&xl, g_xl);
    cudaGetSymbolAddress((void**)&oh, g_oh);
    cudaGetSymbolAddress((void**)&ol, g_ol);
    cudaGetSymbolAddress((void**)&wqh, g_wqh);
    cudaGetSymbolAddress((void**)&wql, g_wql);
    cudaGetSymbolAddress((void**)&wdh, g_wdh);
    cudaGetSymbolAddress((void**)&wdl, g_wdl);

    cudaFuncSetAttribute(attn_kernel,
                         cudaFuncAttributeMaxDynamicSharedMemorySize, ATT_SMEM_BYTES);
    cudaFuncSetAttribute(gemm_bf16x3,
                         cudaFuncAttributeMaxDynamicSharedMemorySize, GEMM_SMEM);

    // 0) fp32 -> bf16 hi/lo conversions
    {
        long n = (long)NB * LQ * KDIM;
        convert_split<<<(unsigned)((n / 4 + 255) / 256), 256>>>(hidden, xh, xl, n, n);
        long nr = (long)NQKV * KDIM, np = (long)NQKV_PAD * KDIM;
        convert_split<<<(unsigned)((np / 4 + 255) / 256), 256>>>(w_qkv, wqh, wql, nr, np);
        nr = (long)DM * KDIM; np = (long)ND_PAD * KDIM;
        convert_split<<<(unsigned)((np / 4 + 255) / 256), 256>>>(w_dense, wdh, wdl, nr, np);
    }

    // 1) QKV GEMM (HMMA bf16x3): (2048 x 4544) * (4736 x 4544)^T -> g_fused
    {
        dim3 grid(NQKV_PAD / 128, (NB * LQ) / 128);
        gemm_bf16x3<<<grid, 256, GEMM_SMEM>>>(xh, xl, wqh, wql,
                                              fused_ptr, FSTRIDE, NQKV_PAD);
    }

    // 2) RoPE
    rope_kernel<<<NB * LQ, 256>>>();

    // 3) Attention
    {
        dim3 grid(LQ / 64, HQ, NB);
        attn_kernel<<<grid, 256, ATT_SMEM_BYTES>>>();
    }

    // 4) attn output -> bf16 hi/lo
    {
        long n = (long)NB * LQ * KDIM;
        convert_split<<<(unsigned)((n / 4 + 255) / 256), 256>>>(attn_ptr, oh, ol, n, n);
    }

    // 5) Dense GEMM (HMMA bf16x3): (2048 x 4544) * (4608 x 4544)^T -> out
    {
        dim3 grid(ND_PAD / 128, (NB * LQ) / 128);
        gemm_bf16x3<<<grid, 256, GEMM_SMEM>>>(oh, ol, wdh, wdl,
                                              out, DM, DM);
    }
}

// round 13
// speedup vs baseline: 2.4863x; 1.1546x over previous
#include <cuda_runtime.h>
#include <cuda_bf16.h>
#include <math.h>
#include <stdint.h>

// Problem constants
#define NB 2
#define LQ 1024
#define DM 4544          // = 71 * 64
#define HQ 71
#define DK 64
#define KDIM 4544
#define NQKV 4672        // DM + 2*DK
#define NQKV_PAD 4736    // 37 * 128
#define ND_PAD 4608      // 36 * 128
#define FSTRIDE NQKV_PAD

// ---------------------------------------------------------------------------
// Scratch (__device__ globals; allocation-free)
// ---------------------------------------------------------------------------
__device__ float g_fused[NB * LQ * FSTRIDE];     // qkv GEMM output (fp32)
__device__ __nv_bfloat16 g_xh[NB * LQ * KDIM];   // hidden hi/lo
__device__ __nv_bfloat16 g_xl[NB * LQ * KDIM];
__device__ __nv_bfloat16 g_oh[NB * LQ * KDIM];   // attn-out hi/lo (written by attn)
__device__ __nv_bfloat16 g_ol[NB * LQ * KDIM];
__device__ __nv_bfloat16 g_wqh[NQKV_PAD * KDIM];
__device__ __nv_bfloat16 g_wql[NQKV_PAD * KDIM];
__device__ __nv_bfloat16 g_wdh[ND_PAD * KDIM];
__device__ __nv_bfloat16 g_wdl[ND_PAD * KDIM];
// rope'd bf16 hi/lo q/k/v
__device__ __nv_bfloat16 g_qh[NB * LQ * DM];
__device__ __nv_bfloat16 g_ql[NB * LQ * DM];
__device__ __nv_bfloat16 g_kh[NB * LQ * DK];
__device__ __nv_bfloat16 g_kl[NB * LQ * DK];
__device__ __nv_bfloat16 g_vh[NB * LQ * DK];
__device__ __nv_bfloat16 g_vl[NB * LQ * DK];

// ---------------------------------------------------------------------------
// PTX helpers (compute_103-safe: cp.async + ldmatrix + mma.sync only)
// ---------------------------------------------------------------------------
__device__ __forceinline__ uint32_t smem_u32(const void* p) {
    uint32_t a;
    asm("{ .reg .u64 t; cvta.to.shared.u64 t, %1; cvt.u32.u64 %0, t; }"
        : "=r"(a) : "l"(p));
    return a;
}

#define CP_ASYNC16(dst, src) \
    asm volatile("cp.async.cg.shared.global [%0], [%1], 16;" \
                 :: "r"(dst), "l"(src) : "memory")
#define CP_COMMIT() asm volatile("cp.async.commit_group;" ::: "memory")
template <int N>
__device__ __forceinline__ void cp_wait_group() {
    asm volatile("cp.async.wait_group %0;" :: "n"(N) : "memory");
}

#define LDSM_X4(r, addr) \
    asm volatile("ldmatrix.sync.aligned.m8n8.x4.shared.b16 {%0,%1,%2,%3}, [%4];" \
                 : "=r"((r)[0]), "=r"((r)[1]), "=r"((r)[2]), "=r"((r)[3]) \
                 : "r"(addr))

#define MMA_BF16(c, a, b) \
    asm volatile("mma.sync.aligned.m16n8k16.row.col.f32.bf16.bf16.f32 " \
                 "{%0,%1,%2,%3}, {%4,%5,%6,%7}, {%8,%9}, {%0,%1,%2,%3};" \
                 : "+f"((c)[0]), "+f"((c)[1]), "+f"((c)[2]), "+f"((c)[3]) \
                 : "r"((a)[0]), "r"((a)[1]), "r"((a)[2]), "r"((a)[3]), \
                   "r"((b)[0]), "r"((b)[1]))

// ---------------------------------------------------------------------------
// fp32 -> bf16 hi/lo split (with zero-padding past n_real)
// ---------------------------------------------------------------------------
__global__ __launch_bounds__(256) void convert_split(
    const float* __restrict__ src, __nv_bfloat16* __restrict__ hh,
    __nv_bfloat16* __restrict__ ll, long n_real, long n_pad)
{
    long idx = ((long)blockIdx.x * 256 + threadIdx.x) * 4;
    if (idx >= n_pad) return;
    float4 v = make_float4(0.f, 0.f, 0.f, 0.f);
    if (idx < n_real) v = *(const float4*)(src + idx);

    __nv_bfloat16 h0 = __float2bfloat16(v.x);
    __nv_bfloat16 h1 = __float2bfloat16(v.y);
    __nv_bfloat16 h2 = __float2bfloat16(v.z);
    __nv_bfloat16 h3 = __float2bfloat16(v.w);
    __nv_bfloat16 l0 = __float2bfloat16(v.x - __bfloat162float(h0));
    __nv_bfloat16 l1 = __float2bfloat16(v.y - __bfloat162float(h1));
    __nv_bfloat16 l2 = __float2bfloat16(v.z - __bfloat162float(h2));
    __nv_bfloat16 l3 = __float2bfloat16(v.w - __bfloat162float(h3));

    __nv_bfloat162 hp0 = __nv_bfloat162(h0, h1), hp1 = __nv_bfloat162(h2, h3);
    __nv_bfloat162 lp0 = __nv_bfloat162(l0, l1), lp1 = __nv_bfloat162(l2, l3);
    *(uint2*)(hh + idx) = make_uint2(*(uint32_t*)&hp0, *(uint32_t*)&hp1);
    *(uint2*)(ll + idx) = make_uint2(*(uint32_t*)&lp0, *(uint32_t*)&lp1);
}

// ---------------------------------------------------------------------------
// HMMA GEMM, bf16x3 split: C[M,N] = A[M,K] * B[N,K]^T
// BM=128, BN=128, BK=32; 8 warps (2m x 4n); 3-stage cp.async pipeline.
// ---------------------------------------------------------------------------
#define BKI 32
#define SKEW 8
#define LDT (BKI + SKEW)             // 40 elements
#define ROWB (LDT * 2)               // 80 bytes per row
#define TILEB (128 * ROWB)           // 10240 bytes
#define STAGEB (4 * TILEB)           // 40960 bytes
#define GEMM_SMEM (3 * STAGEB)       // 122880 bytes
#define NKIT (KDIM / BKI)            // 142

__device__ __forceinline__ void load_stage(
    uint32_t sb, int stage, int k0, int tid, const char* const* srcs)
{
    size_t koff = (size_t)k0 * 2;
#pragma unroll
    for (int t = 0; t < 8; t++) {
        int c    = tid + t * 256;        // 0..2047
        int tile = c >> 9;
        int row  = (c >> 2) & 127;
        int q    = c & 3;
        const char* src = srcs[tile] + (size_t)row * (KDIM * 2) + koff + q * 16;
        uint32_t dst = sb + (uint32_t)stage * STAGEB + (uint32_t)tile * TILEB
                     + (uint32_t)(row * ROWB + q * 16);
        CP_ASYNC16(dst, src);
    }
    CP_COMMIT();
}

__global__ __launch_bounds__(256, 1) void gemm_bf16x3(
    const __nv_bfloat16* __restrict__ Ah, const __nv_bfloat16* __restrict__ Al,
    const __nv_bfloat16* __restrict__ Bh, const __nv_bfloat16* __restrict__ Bl,
    float* __restrict__ C, int ldc, int n_real)
{
    extern __shared__ char smem[];
    uint32_t sb = smem_u32(smem);
    const int tid  = threadIdx.x;
    const int warp = tid >> 5;
    const int lane = tid & 31;
    const int bm = blockIdx.y * 128;
    const int bn = blockIdx.x * 128;

    const int wm = (warp >> 2) * 64;
    const int wn = (warp & 3) * 32;

    const char* srcs[4] = {
        (const char*)Ah + (size_t)bm * KDIM * 2,
        (const char*)Al + (size_t)bm * KDIM * 2,
        (const char*)Bh + (size_t)bn * KDIM * 2,
        (const char*)Bl + (size_t)bn * KDIM * 2
    };

    const int lr = lane & 7;
    const int ma = lane >> 3;
    const uint32_t aoff = (uint32_t)((((ma & 1) * 8 + lr) * LDT + (ma >> 1) * 8) * 2);
    const uint32_t boff = (uint32_t)((((ma >> 1) * 8 + lr) * LDT + (ma & 1) * 8) * 2);

    const uint32_t aBase = sb + (uint32_t)(wm * ROWB) + aoff;
    const uint32_t bBase = sb + 2u * TILEB + (uint32_t)(wn * ROWB) + boff;

    float acc[4][4][4];
#pragma unroll
    for (int i = 0; i < 4; i++)
#pragma unroll
        for (int j = 0; j < 4; j++)
#pragma unroll
            for (int k = 0; k < 4; k++) acc[i][j][k] = 0.0f;

    load_stage(sb, 0, 0, tid, srcs);
    load_stage(sb, 1, BKI, tid, srcs);

    for (int it = 0; it < NKIT; it++) {
        const int s = it % 3;
        if (it == NKIT - 1) cp_wait_group<0>();
        else                cp_wait_group<1>();
        __syncthreads();
        if (it + 2 < NKIT) load_stage(sb, (it + 2) % 3, (it + 2) * BKI, tid, srcs);

        const uint32_t so = (uint32_t)s * STAGEB;
#pragma unroll
        for (int ks = 0; ks < 2; ks++) {
            const uint32_t kb = (uint32_t)(ks * 32);
            uint32_t ah[4][4], al[4][4], bh[4][2], bl[4][2];
#pragma unroll
            for (int mt = 0; mt < 4; mt++) {
                uint32_t a = aBase + so + (uint32_t)(mt * 16 * ROWB) + kb;
                LDSM_X4(ah[mt], a);
                LDSM_X4(al[mt], a + TILEB);
            }
#pragma unroll
            for (int nt2 = 0; nt2 < 2; nt2++) {
                uint32_t b = bBase + so + (uint32_t)(nt2 * 16 * ROWB) + kb;
                LDSM_X4(&bh[nt2 * 2][0], b);
                LDSM_X4(&bl[nt2 * 2][0], b + TILEB);
            }
#pragma unroll
            for (int mt = 0; mt < 4; mt++) {
#pragma unroll
                for (int nt = 0; nt < 4; nt++) {
                    MMA_BF16(acc[mt][nt], ah[mt], bh[nt]);
                    MMA_BF16(acc[mt][nt], ah[mt], bl[nt]);
                    MMA_BF16(acc[mt][nt], al[mt], bh[nt]);
                }
            }
        }
    }

    const int r0 = bm + wm + (lane >> 2);
    const int c0 = bn + wn + (lane & 3) * 2;
#pragma unroll
    for (int mt = 0; mt < 4; mt++) {
#pragma unroll
        for (int nt = 0; nt < 4; nt++) {
            int col = c0 + nt * 8;
            if (col < n_real) {
                int row = r0 + mt * 16;
                *(float2*)(C + (size_t)row * ldc + col) =
                    make_float2(acc[mt][nt][0], acc[mt][nt][1]);
                *(float2*)(C + (size_t)(row + 8) * ldc + col) =
                    make_float2(acc[mt][nt][2], acc[mt][nt][3]);
            }
        }
    }
}

// ---------------------------------------------------------------------------
// RoPE + fp32->bf16 hi/lo conversion of q, k, v from g_fused.
// ---------------------------------------------------------------------------
__global__ __launch_bounds__(256) void rope_convert()
{
    const int token = blockIdx.x;
    const int t = token & (LQ - 1);
    const float* src = g_fused + (size_t)token * FSTRIDE;

    for (int p = threadIdx.x; p < (HQ + 1) * 32; p += 256) {
        int head = p >> 5;
        int j = p & 31;
        const float* hb = src + (head < HQ ? head * DK : DM);
        float inv = powf(10000.0f, -(float)j * (1.0f / 32.0f));
        float ang = (float)t * inv;
        float s, c;
        sincosf(ang, &s, &c);
        float x1 = hb[j], x2 = hb[j + 32];
        float y1 = x1 * c - x2 * s;
        float y2 = x2 * c + x1 * s;
        __nv_bfloat16 h1 = __float2bfloat16(y1);
        __nv_bfloat16 h2 = __float2bfloat16(y2);
        __nv_bfloat16 l1 = __float2bfloat16(y1 - __bfloat162float(h1));
        __nv_bfloat16 l2 = __float2bfloat16(y2 - __bfloat162float(h2));
        if (head < HQ) {
            size_t base = (size_t)token * DM + head * DK;
            g_qh[base + j] = h1;      g_ql[base + j] = l1;
            g_qh[base + j + 32] = h2; g_ql[base + j + 32] = l2;
        } else {
            size_t base = (size_t)token * DK;
            g_kh[base + j] = h1;      g_kl[base + j] = l1;
            g_kh[base + j + 32] = h2; g_kl[base + j + 32] = l2;
        }
    }
    for (int j = threadIdx.x; j < DK; j += 256) {
        float v = src[DM + DK + j];
        __nv_bfloat16 hv = __float2bfloat16(v);
        g_vh[(size_t)token * DK + j] = hv;
        g_vl[(size_t)token * DK + j] = __float2bfloat16(v - __bfloat162float(hv));
    }
}

// ---------------------------------------------------------------------------
// HMMA flash attention, causal, MQA. Block = (qb tile of 64, head, batch).
// 4 warps; warp owns 16 rows. S = Q K^T (hi/lo 3-mma), online softmax on
// fragments, P repacked in regs (hi/lo), O += P V (3-mma, V transposed smem).
// Output written directly as bf16 hi/lo to g_oh/g_ol.
// ---------------------------------------------------------------------------
#define AQH 0
#define AQL 4608
#define AKH 9216
#define AKL 13824
#define AVH 18432
#define AVL 23040
#define ATT_SMEM (6 * 4608 * 2)      // 55296 bytes

__global__ __launch_bounds__(128) void attn_mma()
{
    extern __shared__ __nv_bfloat16 smb[];
    uint32_t sb = smem_u32(smb);
    const int tid = threadIdx.x, warp = tid >> 5, lane = tid & 31;
    const int qb = blockIdx.x, h = blockIdx.y, n = blockIdx.z;

    // Load Q tile (64 x 64 hi/lo), row stride 72 in smem
    {
        const __nv_bfloat16* qsh = g_qh + (size_t)(n * LQ + qb * 64) * DM + h * DK;
        const __nv_bfloat16* qsl = g_ql + (size_t)(n * LQ + qb * 64) * DM + h * DK;
        for (int i = tid; i < 1024; i += 128) {
            int row = i >> 4, c4 = (i & 15) * 4;
            *(uint2*)(smb + AQH + row * 72 + c4) = *(const uint2*)(qsh + (size_t)row * DM + c4);
            *(uint2*)(smb + AQL + row * 72 + c4) = *(const uint2*)(qsl + (size_t)row * DM + c4);
        }
    }

    const int lr = lane & 7, mg = lane >> 3;
    const uint32_t aoff = (uint32_t)((((mg & 1) * 8 + lr) * 72 + (mg >> 1) * 8) * 2);
    const uint32_t boff = (uint32_t)((((mg >> 1) * 8 + lr) * 72 + (mg & 1) * 8) * 2);

    float oacc[8][4];
#pragma unroll
    for (int i = 0; i < 8; i++)
#pragma unroll
        for (int j = 0; j < 4; j++) oacc[i][j] = 0.0f;
    float m0 = -INFINITY, m1 = -INFINITY, l0 = 0.0f, l1 = 0.0f;
    const float scale = 0.125f;
    const int rl0 = warp * 16 + (lane >> 2);
    const int rl1 = rl0 + 8;

    for (int jb = 0; jb <= qb; jb++) {
        __syncthreads();   // protect K/V smem reuse (covers Q load on iter 0)
        {
            const __nv_bfloat16* ksh = g_kh + (size_t)(n * LQ + jb * 64) * DK;
            const __nv_bfloat16* ksl = g_kl + (size_t)(n * LQ + jb * 64) * DK;
            const __nv_bfloat16* vsh = g_vh + (size_t)(n * LQ + jb * 64) * DK;
            const __nv_bfloat16* vsl = g_vl + (size_t)(n * LQ + jb * 64) * DK;
            for (int i = tid; i < 1024; i += 128) {
                int row = i >> 4, c4 = (i & 15) * 4;
                *(uint2*)(smb + AKH + row * 72 + c4) = *(const uint2*)(ksh + row * 64 + c4);
                *(uint2*)(smb + AKL + row * 72 + c4) = *(const uint2*)(ksl + row * 64 + c4);
                uint2 vh4 = *(const uint2*)(vsh + row * 64 + c4);
                uint2 vl4 = *(const uint2*)(vsl + row * 64 + c4);
                const __nv_bfloat16* ph = (const __nv_bfloat16*)&vh4;
                const __nv_bfloat16* pl = (const __nv_bfloat16*)&vl4;
#pragma unroll
                for (int mm = 0; mm < 4; mm++) {
                    smb[AVH + (c4 + mm) * 72 + row] = ph[mm];   // V^T: [d][key]
                    smb[AVL + (c4 + mm) * 72 + row] = pl[mm];
                }
            }
        }
        __syncthreads();

        // S = Q K^T
        float sacc[8][4];
#pragma unroll
        for (int i = 0; i < 8; i++)
#pragma unroll
            for (int j = 0; j < 4; j++) sacc[i][j] = 0.0f;

#pragma unroll
        for (int kb = 0; kb < 4; kb++) {
            uint32_t qa_h[4], qa_l[4];
            uint32_t qaddr = sb + AQH * 2 + (uint32_t)(warp * 16 * 144) + aoff + kb * 32;
            LDSM_X4(qa_h, qaddr);
            LDSM_X4(qa_l, qaddr + (AQL - AQH) * 2);
#pragma unroll
            for (int nt2 = 0; nt2 < 4; nt2++) {
                uint32_t kf_h[4], kf_l[4];
                uint32_t kaddr = sb + AKH * 2 + (uint32_t)(nt2 * 16 * 144) + boff + kb * 32;
                LDSM_X4(kf_h, kaddr);
                LDSM_X4(kf_l, kaddr + (AKL - AKH) * 2);
                MMA_BF16(sacc[nt2 * 2],     qa_h, kf_h);
                MMA_BF16(sacc[nt2 * 2 + 1], qa_h, kf_h + 2);
                MMA_BF16(sacc[nt2 * 2],     qa_h, kf_l);
                MMA_BF16(sacc[nt2 * 2 + 1], qa_h, kf_l + 2);
                MMA_BF16(sacc[nt2 * 2],     qa_l, kf_h);
                MMA_BF16(sacc[nt2 * 2 + 1], qa_l, kf_h + 2);
            }
        }

        // scale + causal mask (diagonal block only)
        const bool diag = (jb == qb);
#pragma unroll
        for (int nt = 0; nt < 8; nt++) {
            int lc = nt * 8 + (lane & 3) * 2;
            if (diag) {
                sacc[nt][0] = (lc     <= rl0) ? sacc[nt][0] * scale : -1e30f;
                sacc[nt][1] = (lc + 1 <= rl0) ? sacc[nt][1] * scale : -1e30f;
                sacc[nt][2] = (lc     <= rl1) ? sacc[nt][2] * scale : -1e30f;
                sacc[nt][3] = (lc + 1 <= rl1) ? sacc[nt][3] * scale : -1e30f;
            } else {
                sacc[nt][0] *= scale; sacc[nt][1] *= scale;
                sacc[nt][2] *= scale; sacc[nt][3] *= scale;
            }
        }

        // online softmax (rows rl0, rl1); reduce across lane&3 quad
        float mx0 = -1e30f, mx1 = -1e30f;
#pragma unroll
        for (int nt = 0; nt < 8; nt++) {
            mx0 = fmaxf(mx0, fmaxf(sacc[nt][0], sacc[nt][1]));
            mx1 = fmaxf(mx1, fmaxf(sacc[nt][2], sacc[nt][3]));
        }
#pragma unroll
        for (int off = 1; off <= 2; off <<= 1) {
            mx0 = fmaxf(mx0, __shfl_xor_sync(0xffffffffu, mx0, off));
            mx1 = fmaxf(mx1, __shfl_xor_sync(0xffffffffu, mx1, off));
        }
        float mn0 = fmaxf(m0, mx0), mn1 = fmaxf(m1, mx1);
        float alpha0 = __expf(m0 - mn0), alpha1 = __expf(m1 - mn1);
        m0 = mn0; m1 = mn1;
        float rs0 = 0.0f, rs1 = 0.0f;
#pragma unroll
        for (int nt = 0; nt < 8; nt++) {
            sacc[nt][0] = __expf(sacc[nt][0] - mn0);
            sacc[nt][1] = __expf(sacc[nt][1] - mn0);
            sacc[nt][2] = __expf(sacc[nt][2] - mn1);
            sacc[nt][3] = __expf(sacc[nt][3] - mn1);
            rs0 += sacc[nt][0] + sacc[nt][1];
            rs1 += sacc[nt][2] + sacc[nt][3];
        }
#pragma unroll
        for (int off = 1; off <= 2; off <<= 1) {
            rs0 += __shfl_xor_sync(0xffffffffu, rs0, off);
            rs1 += __shfl_xor_sync(0xffffffffu, rs1, off);
        }
        l0 = l0 * alpha0 + rs0;
        l1 = l1 * alpha1 + rs1;
#pragma unroll
        for (int dt = 0; dt < 8; dt++) {
            oacc[dt][0] *= alpha0; oacc[dt][1] *= alpha0;
            oacc[dt][2] *= alpha1; oacc[dt][3] *= alpha1;
        }

        // O += P V   (P from sacc, repacked as A-frags in regs, hi/lo)
#pragma unroll
        for (int kb2 = 0; kb2 < 4; kb2++) {
            uint32_t pa_h[4], pa_l[4];
            const int t0 = kb2 * 2, t1 = t0 + 1;
            {
                __nv_bfloat162 hp, lp;
                hp = __floats2bfloat162_rn(sacc[t0][0], sacc[t0][1]);
                lp = __floats2bfloat162_rn(sacc[t0][0] - __bfloat162float(hp.x),
                                           sacc[t0][1] - __bfloat162float(hp.y));
                pa_h[0] = *(uint32_t*)&hp; pa_l[0] = *(uint32_t*)&lp;
                hp = __floats2bfloat162_rn(sacc[t0][2], sacc[t0][3]);
                lp = __floats2bfloat162_rn(sacc[t0][2] - __bfloat162float(hp.x),
                                           sacc[t0][3] - __bfloat162float(hp.y));
                pa_h[1] = *(uint32_t*)&hp; pa_l[1] = *(uint32_t*)&lp;
                hp = __floats2bfloat162_rn(sacc[t1][0], sacc[t1][1]);
                lp = __floats2bfloat162_rn(sacc[t1][0] - __bfloat162float(hp.x),
                                           sacc[t1][1] - __bfloat162float(hp.y));
                pa_h[2] = *(uint32_t*)&hp; pa_l[2] = *(uint32_t*)&lp;
                hp = __floats2bfloat162_rn(sacc[t1][2], sacc[t1][3]);
                lp = __floats2bfloat162_rn(sacc[t1][2] - __bfloat162float(hp.x),
                                           sacc[t1][3] - __bfloat162float(hp.y));
                pa_h[3] = *(uint32_t*)&hp; pa_l[3] = *(uint32_t*)&lp;
            }
#pragma unroll
            for (int dt2 = 0; dt2 < 4; dt2++) {
                uint32_t vf_h[4], vf_l[4];
                uint32_t vaddr = sb + AVH * 2 + (uint32_t)(dt2 * 16 * 144) + boff + kb2 * 32;
                LDSM_X4(vf_h, vaddr);
                LDSM_X4(vf_l, vaddr + (AVL - AVH) * 2);
                MMA_BF16(oacc[dt2 * 2],     pa_h, vf_h);
                MMA_BF16(oacc[dt2 * 2 + 1], pa_h, vf_h + 2);
                MMA_BF16(oacc[dt2 * 2],     pa_h, vf_l);
                MMA_BF16(oacc[dt2 * 2 + 1], pa_h, vf_l + 2);
                MMA_BF16(oacc[dt2 * 2],     pa_l, vf_h);
                MMA_BF16(oacc[dt2 * 2 + 1], pa_l, vf_h + 2);
            }
        }
    }

    // Epilogue: normalize, write bf16 hi/lo directly
    const float inv0 = 1.0f / l0, inv1 = 1.0f / l1;
    const size_t tok0 = (size_t)(n * LQ + qb * 64 + rl0);
    const size_t tok1 = tok0 + 8;
#pragma unroll
    for (int dt = 0; dt < 8; dt++) {
        int col = h * DK + dt * 8 + (lane & 3) * 2;
        float o0 = oacc[dt][0] * inv0, o1 = oacc[dt][1] * inv0;
        __nv_bfloat162 hp = __floats2bfloat162_rn(o0, o1);
        __nv_bfloat162 lp = __floats2bfloat162_rn(o0 - __bfloat162float(hp.x),
                                                  o1 - __bfloat162float(hp.y));
        *(__nv_bfloat162*)(g_oh + tok0 * KDIM + col) = hp;
        *(__nv_bfloat162*)(g_ol + tok0 * KDIM + col) = lp;
        o0 = oacc[dt][2] * inv1; o1 = oacc[dt][3] * inv1;
        hp = __floats2bfloat162_rn(o0, o1);
        lp = __floats2bfloat162_rn(o0 - __bfloat162float(hp.x),
                                   o1 - __bfloat162float(hp.y));
        *(__nv_bfloat162*)(g_oh + tok1 * KDIM + col) = hp;
        *(__nv_bfloat162*)(g_ol + tok1 * KDIM + col) = lp;
    }
}

// ---------------------------------------------------------------------------
// Launch
// ---------------------------------------------------------------------------
extern "C" void kernel_launch(void* const* d_in, const int* in_sizes, int n_in,
                              void* d_out, int out_size)
{
    const float* hidden  = (const float*)d_in[0];
    const float* w_qkv   = (const float*)d_in[1];
    const float* w_dense = (const float*)d_in[2];
    float* out = (float*)d_out;

    float* fused_ptr;
    __nv_bfloat16 *xh, *xl, *oh, *ol, *wqh, *wql, *wdh, *wdl;
    cudaGetSymbolAddress((void**)&fused_ptr, g_fused);
    cudaGetSymbolAddress((void**)&xh, g_xh);
    cudaGetSymbolAddress((void**)&xl, g_xl);
    cudaGetSymbolAddress((void**)&oh, g_oh);
    cudaGetSymbolAddress((void**)&ol, g_ol);
    cudaGetSymbolAddress((void**)&wqh, g_wqh);
    cudaGetSymbolAddress((void**)&wql, g_wql);
    cudaGetSymbolAddress((void**)&wdh, g_wdh);
    cudaGetSymbolAddress((void**)&wdl, g_wdl);

    cudaFuncSetAttribute(gemm_bf16x3,
                         cudaFuncAttributeMaxDynamicSharedMemorySize, GEMM_SMEM);
    cudaFuncSetAttribute(attn_mma,
                         cudaFuncAttributeMaxDynamicSharedMemorySize, ATT_SMEM);

    // 0) fp32 -> bf16 hi/lo conversions
    {
        long n = (long)NB * LQ * KDIM;
        convert_split<<<(unsigned)((n / 4 + 255) / 256), 256>>>(hidden, xh, xl, n, n);
        long nr = (long)NQKV * KDIM, np = (long)NQKV_PAD * KDIM;
        convert_split<<<(unsigned)((np / 4 + 255) / 256), 256>>>(w_qkv, wqh, wql, nr, np);
        nr = (long)DM * KDIM; np = (long)ND_PAD * KDIM;
        convert_split<<<(unsigned)((np / 4 + 255) / 256), 256>>>(w_dense, wdh, wdl, nr, np);
    }

    // 1) QKV GEMM
    {
        dim3 grid(NQKV_PAD / 128, (NB * LQ) / 128);
        gemm_bf16x3<<<grid, 256, GEMM_SMEM>>>(xh, xl, wqh, wql,
                                              fused_ptr, FSTRIDE, NQKV_PAD);
    }

    // 2) RoPE + bf16 hi/lo q/k/v
    rope_convert<<<NB * LQ, 256>>>();

    // 3) HMMA flash attention -> g_oh/g_ol
    {
        dim3 grid(LQ / 64, HQ, NB);
        attn_mma<<<grid, 128, ATT_SMEM>>>();
    }

    // 4) Dense GEMM
    {
        dim3 grid(ND_PAD / 128, (NB * LQ) / 128);
        gemm_bf16x3<<<grid, 256, GEMM_SMEM>>>(oh, ol, wdh, wdl,
                                              out, DM, DM);
    }
}